// round 5
// baseline (speedup 1.0000x reference)
#include <cuda_runtime.h>
#include <cuda_bf16.h>
#include <cstdint>

#define DIM 128
#define TILE_M 128
#define MAX_N 1000000

__device__ float g_scores[MAX_N];

// ---------------- smem layout (kernel 1) ----------------
#define OFF_STAGE 0
#define OFF_A_HI  65536
#define OFF_A_LO  98304
#define OFF_W_HI  131072
#define OFF_W_LO  163840
#define OFF_B     196608
#define OFF_CTX   197120
#define OFF_SRED  197632          // float [2][128]
#define SMEM_TOTAL (197632 + 1024)

// ---------------- helpers ----------------
__device__ __forceinline__ uint32_t smem_to_u32(const void* p) {
    uint32_t a;
    asm("{ .reg .u64 t; cvta.to.shared.u64 t, %1; cvt.u32.u64 %0, t; }"
        : "=r"(a) : "l"(p));
    return a;
}

// swizzled bf16 tile address: row-major, 256B/row (128 bf16), 16B chunks XOR'd by row&7
__device__ __forceinline__ uint32_t sw_addr(uint32_t base, int row, int kchunk) {
    return base + (uint32_t)row * 256u + (uint32_t)((kchunk ^ (row & 7)) << 4);
}

__device__ __forceinline__ void ldsm4(uint32_t* r, uint32_t addr) {
    asm volatile("ldmatrix.sync.aligned.m8n8.x4.shared.b16 {%0,%1,%2,%3}, [%4];"
        : "=r"(r[0]), "=r"(r[1]), "=r"(r[2]), "=r"(r[3]) : "r"(addr));
}

__device__ __forceinline__ void mma_bf16(float* d, const uint32_t* a, const uint32_t* b) {
    asm volatile(
        "mma.sync.aligned.m16n8k16.row.col.f32.bf16.bf16.f32 "
        "{%0,%1,%2,%3}, {%4,%5,%6,%7}, {%8,%9}, {%0,%1,%2,%3};"
        : "+f"(d[0]), "+f"(d[1]), "+f"(d[2]), "+f"(d[3])
        : "r"(a[0]), "r"(a[1]), "r"(a[2]), "r"(a[3]), "r"(b[0]), "r"(b[1]));
}

__device__ __forceinline__ void cp_async16(uint32_t saddr, const void* gaddr, int srcsize) {
    asm volatile("cp.async.cg.shared.global [%0], [%1], 16, %2;"
        :: "r"(saddr), "l"(gaddr), "r"(srcsize) : "memory");
}
__device__ __forceinline__ void cp_commit() {
    asm volatile("cp.async.commit_group;" ::: "memory");
}
__device__ __forceinline__ void cp_wait_all() {
    asm volatile("cp.async.wait_group 0;" ::: "memory");
}

union BfU { __nv_bfloat162 b; uint32_t u; };

// Truncation split: hi = x with low 16 mantissa bits cleared (exact bf16 bit
// pattern = top 16 bits). lo = x - hi is EXACT in fp32, then rounded to bf16.
// Residual after 3-term MMA = a_lo*w_lo ~ 2^-16 relative -> negligible.
__device__ __forceinline__ void split_store(char* smem, uint32_t hi_off, uint32_t lo_off,
                                            int r, int q, float4 v) {
    uint32_t xu0 = __float_as_uint(v.x), xu1 = __float_as_uint(v.y);
    uint32_t xu2 = __float_as_uint(v.z), xu3 = __float_as_uint(v.w);
    uint32_t hi01 = (xu0 >> 16) | (xu1 & 0xFFFF0000u);   // [bf16(x0) | bf16(x1)]
    uint32_t hi23 = (xu2 >> 16) | (xu3 & 0xFFFF0000u);
    float l0f = v.x - __uint_as_float(xu0 & 0xFFFF0000u);
    float l1f = v.y - __uint_as_float(xu1 & 0xFFFF0000u);
    float l2f = v.z - __uint_as_float(xu2 & 0xFFFF0000u);
    float l3f = v.w - __uint_as_float(xu3 & 0xFFFF0000u);
    BfU lo01, lo23;
    lo01.b = __floats2bfloat162_rn(l0f, l1f);
    lo23.b = __floats2bfloat162_rn(l2f, l3f);
    uint32_t boff = (uint32_t)r * 256u + (uint32_t)(((q >> 1) ^ (r & 7)) << 4)
                  + (uint32_t)((q & 1) << 3);
    *(uint2*)(smem + hi_off + boff) = make_uint2(hi01, hi23);
    *(uint2*)(smem + lo_off + boff) = make_uint2(lo01.u, lo23.u);
}

// accurate tanh, immune to --use_fast_math (explicit intrinsics): abs err ~1e-6
__device__ __forceinline__ float tanh_acc(float x) {
    float ax = fabsf(x);
    float e  = __expf(-2.0f * ax);
    float r  = (1.0f - e) * __fdividef(1.0f, 1.0f + e);
    return copysignf(r, x);
}

// ================= Kernel 1: scores = tanh(h W^T + b) . context =================
// 256 threads = 8 warps: warp w -> m-block (w&3)*32 rows, n-block (w>>2)*64 cols.
__global__ void __launch_bounds__(256, 1)
score_kernel(const float* __restrict__ h, const float* __restrict__ W,
             const float* __restrict__ b, const float* __restrict__ ctx, int n)
{
    extern __shared__ char smem[];
    uint32_t sb = smem_to_u32(smem);
    int tid = threadIdx.x;
    int wid = tid >> 5, lane = tid & 31;
    int mb = wid & 3, nb = wid >> 2;

    // ---- prologue: W split (swizzled), b, ctx ----
    for (int idx = tid; idx < TILE_M * 32; idx += 256) {
        int r = idx >> 5, q = idx & 31;
        float4 v = *(const float4*)(W + (size_t)r * DIM + q * 4);
        split_store(smem, OFF_W_HI, OFF_W_LO, r, q, v);
    }
    if (tid < DIM) {
        ((float*)(smem + OFF_B))[tid]   = b[tid];
        ((float*)(smem + OFF_CTX))[tid] = ctx[tid];
    }

    const float* bs   = (const float*)(smem + OFF_B);
    const float* cs   = (const float*)(smem + OFF_CTX);
    float*       sred = (float*)(smem + OFF_SRED);

    int ntiles = (n + TILE_M - 1) / TILE_M;

    // issue cp.async for first tile
    int t0 = blockIdx.x;
    if (t0 < ntiles) {
        int m0 = t0 * TILE_M, valid = min(TILE_M, n - m0);
        const char* src = (const char*)(h + (size_t)m0 * DIM);
        #pragma unroll
        for (int it = 0; it < 16; it++) {
            int chunk = tid + it * 256;           // 16B chunks, 32 per row
            int r = chunk >> 5;
            int sz = (r < valid) ? 16 : 0;
            cp_async16(sb + OFF_STAGE + chunk * 16, src + (size_t)chunk * 16, sz);
        }
        cp_commit();
    }
    __syncthreads();

    for (int t = t0; t < ntiles; t += gridDim.x) {
        int m0 = t * TILE_M;

        // ---- wait tile data, convert stage -> A hi/lo ----
        cp_wait_all();
        __syncthreads();
        #pragma unroll
        for (int it = 0; it < 16; it++) {
            int idx = tid + it * 256;
            int r = idx >> 5, q = idx & 31;
            float4 v = *(const float4*)(smem + OFF_STAGE + (size_t)idx * 16);
            split_store(smem, OFF_A_HI, OFF_A_LO, r, q, v);
        }
        __syncthreads();

        // ---- prefetch next tile ----
        int tn = t + gridDim.x;
        if (tn < ntiles) {
            int mn = tn * TILE_M, valid = min(TILE_M, n - mn);
            const char* src = (const char*)(h + (size_t)mn * DIM);
            #pragma unroll
            for (int it = 0; it < 16; it++) {
                int chunk = tid + it * 256;
                int r = chunk >> 5;
                int sz = (r < valid) ? 16 : 0;
                cp_async16(sb + OFF_STAGE + chunk * 16, src + (size_t)chunk * 16, sz);
            }
            cp_commit();
        }

        // ---- MMA: z = A_hi Wh^T + A_lo Wh^T + A_hi Wl^T ----
        float acc[2][8][4];
        #pragma unroll
        for (int mt = 0; mt < 2; mt++)
            #pragma unroll
            for (int j = 0; j < 8; j++)
                #pragma unroll
                for (int e = 0; e < 4; e++) acc[mt][j][e] = 0.f;

        #pragma unroll
        for (int ks = 0; ks < 8; ks++) {
            uint32_t a_hi[2][4], a_lo[2][4], b_hi[8][2], b_lo[8][2];

            // A frags: m16k16 at rows mb*32 + mt*16, k = ks*16
            #pragma unroll
            for (int mt = 0; mt < 2; mt++) {
                int row = mb * 32 + mt * 16 + (lane & 15);
                int kch = ks * 2 + (lane >> 4);
                ldsm4(a_hi[mt], sw_addr(sb + OFF_A_HI, row, kch));
                ldsm4(a_lo[mt], sw_addr(sb + OFF_A_LO, row, kch));
            }
            // B frags: pairs of n8 tiles (x4 = two n8 frags)
            #pragma unroll
            for (int p = 0; p < 4; p++) {
                int row = nb * 64 + p * 16 + (lane & 7) + ((lane >> 4) << 3);
                int kch = ks * 2 + ((lane >> 3) & 1);
                uint32_t r4[4];
                ldsm4(r4, sw_addr(sb + OFF_W_HI, row, kch));
                b_hi[2 * p][0] = r4[0]; b_hi[2 * p][1] = r4[1];
                b_hi[2 * p + 1][0] = r4[2]; b_hi[2 * p + 1][1] = r4[3];
                ldsm4(r4, sw_addr(sb + OFF_W_LO, row, kch));
                b_lo[2 * p][0] = r4[0]; b_lo[2 * p][1] = r4[1];
                b_lo[2 * p + 1][0] = r4[2]; b_lo[2 * p + 1][1] = r4[3];
            }
            #pragma unroll
            for (int mt = 0; mt < 2; mt++)
                #pragma unroll
                for (int j = 0; j < 8; j++) {
                    mma_bf16(acc[mt][j], a_hi[mt], b_hi[j]);
                    mma_bf16(acc[mt][j], a_lo[mt], b_hi[j]);
                    mma_bf16(acc[mt][j], a_hi[mt], b_lo[j]);
                }
        }

        // ---- epilogue: s[row] = sum_c tanh(z+b[c])*ctx[c] ----
        #pragma unroll
        for (int mt = 0; mt < 2; mt++) {
            float p0 = 0.f, p1 = 0.f;   // rows base+lane/4, +8
            #pragma unroll
            for (int j = 0; j < 8; j++) {
                int c0 = nb * 64 + j * 8 + (lane & 3) * 2;
                float bb0 = bs[c0],   cc0 = cs[c0];
                float bb1 = bs[c0+1], cc1 = cs[c0+1];
                p0 += tanh_acc(acc[mt][j][0] + bb0) * cc0
                    + tanh_acc(acc[mt][j][1] + bb1) * cc1;
                p1 += tanh_acc(acc[mt][j][2] + bb0) * cc0
                    + tanh_acc(acc[mt][j][3] + bb1) * cc1;
            }
            p0 += __shfl_xor_sync(0xffffffffu, p0, 1);
            p0 += __shfl_xor_sync(0xffffffffu, p0, 2);
            p1 += __shfl_xor_sync(0xffffffffu, p1, 1);
            p1 += __shfl_xor_sync(0xffffffffu, p1, 2);
            if ((lane & 3) == 0) {
                int r0 = mb * 32 + mt * 16 + (lane >> 2);
                sred[nb * 128 + r0]     = p0;
                sred[nb * 128 + r0 + 8] = p1;
            }
        }
        __syncthreads();
        if (tid < 128) {
            int m = m0 + tid;
            if (m < n) g_scores[m] = sred[tid] + sred[128 + tid];
        }
        // next iteration's cp_wait_all + __syncthreads separates sred/A reuse
    }
}

// ======= Kernel 2: per-segment softmax + weighted pool =======
__global__ void __launch_bounds__(128)
pool_kernel(const float* __restrict__ h, const int* __restrict__ blk,
            float* __restrict__ h_file, float* __restrict__ alpha, int n)
{
    int k = blockIdx.x;
    int s = blk[k], e = blk[k + 1];
    int t = threadIdx.x, wid = t >> 5, lid = t & 31;
    __shared__ float red[4];

    if (e - s <= 0) {
        h_file[(size_t)k * DIM + t] = 0.f;
        return;
    }

    // pass 1: max
    float m = -3.402823466e38f;
    for (int i = s + t; i < e; i += 128) m = fmaxf(m, g_scores[i]);
    #pragma unroll
    for (int o = 16; o; o >>= 1) m = fmaxf(m, __shfl_xor_sync(0xffffffffu, m, o));
    if (lid == 0) red[wid] = m;
    __syncthreads();
    m = fmaxf(fmaxf(red[0], red[1]), fmaxf(red[2], red[3]));
    __syncthreads();

    // pass 2: sum of exp; stash raw exp into alpha
    float sum = 0.f;
    for (int i = s + t; i < e; i += 128) {
        float ev = __expf(g_scores[i] - m);
        alpha[i] = ev;
        sum += ev;
    }
    #pragma unroll
    for (int o = 16; o; o >>= 1) sum += __shfl_xor_sync(0xffffffffu, sum, o);
    if (lid == 0) red[wid] = sum;
    __syncthreads();   // orders pass-2 alpha writes before pass-3 reads
    sum = red[0] + red[1] + red[2] + red[3];
    float inv = 1.0f / sum;

    // pass 3: h_file[k][t] = inv * sum_i exp_i * h[i][t]
    float acc = 0.f;
    int i = s;
    for (; i + 3 < e; i += 4) {
        float a0 = alpha[i],     a1 = alpha[i + 1];
        float a2 = alpha[i + 2], a3 = alpha[i + 3];
        acc += a0 * h[(size_t)i       * DIM + t];
        acc += a1 * h[(size_t)(i + 1) * DIM + t];
        acc += a2 * h[(size_t)(i + 2) * DIM + t];
        acc += a3 * h[(size_t)(i + 3) * DIM + t];
    }
    for (; i < e; i++) acc += alpha[i] * h[(size_t)i * DIM + t];
    h_file[(size_t)k * DIM + t] = acc * inv;

    // RACE FIX: all pass-3 reads of raw alpha must complete before any thread
    // scales alpha in place (previously a fast warp scaled entries a slow warp
    // was still reading -> ~1e-2 corruption of h_file).
    __syncthreads();

    for (int j = s + t; j < e; j += 128) alpha[j] *= inv;
}

// ================= launch =================
extern "C" void kernel_launch(void* const* d_in, const int* in_sizes, int n_in,
                              void* d_out, int out_size)
{
    const float* h   = (const float*)d_in[0];
    const float* W   = (const float*)d_in[1];
    const float* b   = (const float*)d_in[2];
    const float* ctx = (const float*)d_in[3];
    const int*   blk = (const int*)d_in[4];

    int n = in_sizes[0] / DIM;
    if (n > MAX_N) n = MAX_N;
    int B = in_sizes[4] - 1;

    float* out    = (float*)d_out;
    float* h_file = out;
    float* alpha  = out + (size_t)B * DIM;

    cudaFuncSetAttribute(score_kernel,
                         cudaFuncAttributeMaxDynamicSharedMemorySize, SMEM_TOTAL);

    int dev = 0, nsm = 148;
    cudaGetDevice(&dev);
    cudaDeviceGetAttribute(&nsm, cudaDevAttrMultiProcessorCount, dev);

    int ntiles = (n + TILE_M - 1) / TILE_M;
    int grid1 = (nsm < ntiles) ? nsm : ntiles;

    score_kernel<<<grid1, 256, SMEM_TOTAL>>>(h, W, b, ctx, n);
    pool_kernel<<<B, 128>>>(h, blk, h_file, alpha, n);
}

// round 7
// speedup vs baseline: 1.0767x; 1.0767x over previous
#include <cuda_runtime.h>
#include <cuda_bf16.h>
#include <cstdint>

#define DIM 128
#define TILE_M 128
#define MAX_N 1000000
#define CHUNK 512

__device__ float g_scores[MAX_N];

// ---------------- smem layout (kernel 1) ----------------
#define OFF_STAGE 0
#define OFF_A_HI  65536
#define OFF_A_LO  98304
#define OFF_W_HI  131072
#define OFF_W_LO  163840
#define OFF_BK    196608          // b[c] * 2*log2(e)
#define OFF_C2    197120          // -2 * ctx[c]
#define OFF_SRED  197632          // float [2][128]
#define SMEM_TOTAL (197632 + 1024)

#define K2LOG2E 2.8853900817779268f

// ---------------- helpers ----------------
__device__ __forceinline__ uint32_t smem_to_u32(const void* p) {
    uint32_t a;
    asm("{ .reg .u64 t; cvta.to.shared.u64 t, %1; cvt.u32.u64 %0, t; }"
        : "=r"(a) : "l"(p));
    return a;
}

__device__ __forceinline__ float ex2f(float x) {
    float y; asm("ex2.approx.f32 %0, %1;" : "=f"(y) : "f"(x)); return y;
}
__device__ __forceinline__ float rcpf(float x) {
    float y; asm("rcp.approx.f32 %0, %1;" : "=f"(y) : "f"(x)); return y;
}

// swizzled bf16 tile address: row-major, 256B/row (128 bf16), 16B chunks XOR'd by row&7
__device__ __forceinline__ uint32_t sw_addr(uint32_t base, int row, int kchunk) {
    return base + (uint32_t)row * 256u + (uint32_t)((kchunk ^ (row & 7)) << 4);
}

__device__ __forceinline__ void ldsm4(uint32_t* r, uint32_t addr) {
    asm volatile("ldmatrix.sync.aligned.m8n8.x4.shared.b16 {%0,%1,%2,%3}, [%4];"
        : "=r"(r[0]), "=r"(r[1]), "=r"(r[2]), "=r"(r[3]) : "r"(addr));
}

__device__ __forceinline__ void mma_bf16(float* d, const uint32_t* a, const uint32_t* b) {
    asm volatile(
        "mma.sync.aligned.m16n8k16.row.col.f32.bf16.bf16.f32 "
        "{%0,%1,%2,%3}, {%4,%5,%6,%7}, {%8,%9}, {%0,%1,%2,%3};"
        : "+f"(d[0]), "+f"(d[1]), "+f"(d[2]), "+f"(d[3])
        : "r"(a[0]), "r"(a[1]), "r"(a[2]), "r"(a[3]), "r"(b[0]), "r"(b[1]));
}

__device__ __forceinline__ void cp_async16(uint32_t saddr, const void* gaddr, int srcsize) {
    asm volatile("cp.async.cg.shared.global [%0], [%1], 16, %2;"
        :: "r"(saddr), "l"(gaddr), "r"(srcsize) : "memory");
}
__device__ __forceinline__ void cp_commit() {
    asm volatile("cp.async.commit_group;" ::: "memory");
}
__device__ __forceinline__ void cp_wait_all() {
    asm volatile("cp.async.wait_group 0;" ::: "memory");
}

union BfU { __nv_bfloat162 b; uint32_t u; };

// Truncation split: hi = top-16-bits bf16 (exact), lo = x - hi (exact fp32) -> bf16 RN.
__device__ __forceinline__ void split_store(char* smem, uint32_t hi_off, uint32_t lo_off,
                                            int r, int q, float4 v) {
    uint32_t xu0 = __float_as_uint(v.x), xu1 = __float_as_uint(v.y);
    uint32_t xu2 = __float_as_uint(v.z), xu3 = __float_as_uint(v.w);
    uint32_t hi01 = (xu0 >> 16) | (xu1 & 0xFFFF0000u);
    uint32_t hi23 = (xu2 >> 16) | (xu3 & 0xFFFF0000u);
    float l0f = v.x - __uint_as_float(xu0 & 0xFFFF0000u);
    float l1f = v.y - __uint_as_float(xu1 & 0xFFFF0000u);
    float l2f = v.z - __uint_as_float(xu2 & 0xFFFF0000u);
    float l3f = v.w - __uint_as_float(xu3 & 0xFFFF0000u);
    BfU lo01, lo23;
    lo01.b = __floats2bfloat162_rn(l0f, l1f);
    lo23.b = __floats2bfloat162_rn(l2f, l3f);
    uint32_t boff = (uint32_t)r * 256u + (uint32_t)(((q >> 1) ^ (r & 7)) << 4)
                  + (uint32_t)((q & 1) << 3);
    *(uint2*)(smem + hi_off + boff) = make_uint2(hi01, hi23);
    *(uint2*)(smem + lo_off + boff) = make_uint2(lo01.u, lo23.u);
}

// ================= Kernel 1: scores = tanh(h W^T + b) . context =================
// 256 threads = 8 warps: warp w -> m-block (w&3)*32 rows, n-block (w>>2)*64 cols.
__global__ void __launch_bounds__(256, 1)
score_kernel(const float* __restrict__ h, const float* __restrict__ W,
             const float* __restrict__ b, const float* __restrict__ ctx, int n)
{
    extern __shared__ char smem[];
    uint32_t sb = smem_to_u32(smem);
    int tid = threadIdx.x;
    int wid = tid >> 5, lane = tid & 31;
    int mb = wid & 3, nb = wid >> 2;

    // ---- prologue: W split (swizzled), transformed b/ctx ----
    for (int idx = tid; idx < TILE_M * 32; idx += 256) {
        int r = idx >> 5, q = idx & 31;
        float4 v = *(const float4*)(W + (size_t)r * DIM + q * 4);
        split_store(smem, OFF_W_HI, OFF_W_LO, r, q, v);
    }
    if (tid < DIM) {
        ((float*)(smem + OFF_BK))[tid] = b[tid] * K2LOG2E;
        ((float*)(smem + OFF_C2))[tid] = -2.0f * ctx[tid];
    }

    // per-thread csum = sum of ctx over this thread's 16 columns
    float csum = 0.f;
    {
        int cbase = nb * 64 + (lane & 3) * 2;
        #pragma unroll
        for (int j = 0; j < 8; j++) {
            csum += ctx[cbase + j * 8] + ctx[cbase + j * 8 + 1];
        }
    }

    const float* bkp  = (const float*)(smem + OFF_BK);
    const float* c2p  = (const float*)(smem + OFF_C2);
    float*       sred = (float*)(smem + OFF_SRED);

    int ntiles = (n + TILE_M - 1) / TILE_M;

    // issue cp.async for first tile
    int t0 = blockIdx.x;
    if (t0 < ntiles) {
        int m0 = t0 * TILE_M, valid = min(TILE_M, n - m0);
        const char* src = (const char*)(h + (size_t)m0 * DIM);
        #pragma unroll
        for (int it = 0; it < 16; it++) {
            int chunk = tid + it * 256;
            int r = chunk >> 5;
            int sz = (r < valid) ? 16 : 0;
            cp_async16(sb + OFF_STAGE + chunk * 16, src + (size_t)chunk * 16, sz);
        }
        cp_commit();
    }
    __syncthreads();

    for (int t = t0; t < ntiles; t += gridDim.x) {
        int m0 = t * TILE_M;

        // ---- wait tile data, convert stage -> A hi/lo ----
        cp_wait_all();
        __syncthreads();
        #pragma unroll
        for (int it = 0; it < 16; it++) {
            int idx = tid + it * 256;
            int r = idx >> 5, q = idx & 31;
            float4 v = *(const float4*)(smem + OFF_STAGE + (size_t)idx * 16);
            split_store(smem, OFF_A_HI, OFF_A_LO, r, q, v);
        }
        __syncthreads();

        // ---- prefetch next tile ----
        int tn = t + gridDim.x;
        if (tn < ntiles) {
            int mn = tn * TILE_M, valid = min(TILE_M, n - mn);
            const char* src = (const char*)(h + (size_t)mn * DIM);
            #pragma unroll
            for (int it = 0; it < 16; it++) {
                int chunk = tid + it * 256;
                int r = chunk >> 5;
                int sz = (r < valid) ? 16 : 0;
                cp_async16(sb + OFF_STAGE + chunk * 16, src + (size_t)chunk * 16, sz);
            }
            cp_commit();
        }

        // ---- MMA: z = A_hi Wh^T + A_lo Wh^T + A_hi Wl^T ----
        float acc[2][8][4];
        #pragma unroll
        for (int mt = 0; mt < 2; mt++)
            #pragma unroll
            for (int j = 0; j < 8; j++)
                #pragma unroll
                for (int e = 0; e < 4; e++) acc[mt][j][e] = 0.f;

        #pragma unroll
        for (int ks = 0; ks < 8; ks++) {
            uint32_t a_hi[2][4], a_lo[2][4], b_hi[8][2], b_lo[8][2];

            #pragma unroll
            for (int mt = 0; mt < 2; mt++) {
                int row = mb * 32 + mt * 16 + (lane & 15);
                int kch = ks * 2 + (lane >> 4);
                ldsm4(a_hi[mt], sw_addr(sb + OFF_A_HI, row, kch));
                ldsm4(a_lo[mt], sw_addr(sb + OFF_A_LO, row, kch));
            }
            #pragma unroll
            for (int p = 0; p < 4; p++) {
                int row = nb * 64 + p * 16 + (lane & 7) + ((lane >> 4) << 3);
                int kch = ks * 2 + ((lane >> 3) & 1);
                uint32_t r4[4];
                ldsm4(r4, sw_addr(sb + OFF_W_HI, row, kch));
                b_hi[2 * p][0] = r4[0]; b_hi[2 * p][1] = r4[1];
                b_hi[2 * p + 1][0] = r4[2]; b_hi[2 * p + 1][1] = r4[3];
                ldsm4(r4, sw_addr(sb + OFF_W_LO, row, kch));
                b_lo[2 * p][0] = r4[0]; b_lo[2 * p][1] = r4[1];
                b_lo[2 * p + 1][0] = r4[2]; b_lo[2 * p + 1][1] = r4[3];
            }
            #pragma unroll
            for (int mt = 0; mt < 2; mt++)
                #pragma unroll
                for (int j = 0; j < 8; j++) {
                    mma_bf16(acc[mt][j], a_hi[mt], b_hi[j]);
                    mma_bf16(acc[mt][j], a_lo[mt], b_hi[j]);
                    mma_bf16(acc[mt][j], a_hi[mt], b_lo[j]);
                }
        }

        // ---- epilogue: tanh(x) = 1 - 2/(1+e^{2x}); per elem 3 FFMA + EX2 + RCP ----
        // p = csum + sum_c rcp(1 + ex2(z*K2 + bk[c])) * (-2*ctx[c])
        float p0 = csum, p1 = csum, p2 = csum, p3 = csum;
        #pragma unroll
        for (int j = 0; j < 8; j++) {
            int c0 = nb * 64 + j * 8 + (lane & 3) * 2;
            float bk0 = bkp[c0], bk1 = bkp[c0 + 1];
            float c20 = c2p[c0], c21 = c2p[c0 + 1];
            p0 += rcpf(1.0f + ex2f(fmaf(acc[0][j][0], K2LOG2E, bk0))) * c20
                + rcpf(1.0f + ex2f(fmaf(acc[0][j][1], K2LOG2E, bk1))) * c21;
            p1 += rcpf(1.0f + ex2f(fmaf(acc[0][j][2], K2LOG2E, bk0))) * c20
                + rcpf(1.0f + ex2f(fmaf(acc[0][j][3], K2LOG2E, bk1))) * c21;
            p2 += rcpf(1.0f + ex2f(fmaf(acc[1][j][0], K2LOG2E, bk0))) * c20
                + rcpf(1.0f + ex2f(fmaf(acc[1][j][1], K2LOG2E, bk1))) * c21;
            p3 += rcpf(1.0f + ex2f(fmaf(acc[1][j][2], K2LOG2E, bk0))) * c20
                + rcpf(1.0f + ex2f(fmaf(acc[1][j][3], K2LOG2E, bk1))) * c21;
        }
        #pragma unroll
        for (int o = 1; o <= 2; o <<= 1) {
            p0 += __shfl_xor_sync(0xffffffffu, p0, o);
            p1 += __shfl_xor_sync(0xffffffffu, p1, o);
            p2 += __shfl_xor_sync(0xffffffffu, p2, o);
            p3 += __shfl_xor_sync(0xffffffffu, p3, o);
        }
        if ((lane & 3) == 0) {
            int r0 = mb * 32 + (lane >> 2);
            sred[nb * 128 + r0]      = p0;
            sred[nb * 128 + r0 + 8]  = p1;
            sred[nb * 128 + r0 + 16] = p2;
            sred[nb * 128 + r0 + 24] = p3;
        }
        __syncthreads();
        if (tid < 128) {
            int m = m0 + tid;
            if (m < n) g_scores[m] = sred[tid] + sred[128 + tid];
        }
    }
}

// ======= Kernel 2a: per-segment softmax stats -> normalized alpha; zero h_file =======
__global__ void __launch_bounds__(128)
seg_stats_kernel(const int* __restrict__ blk, float* __restrict__ h_file,
                 float* __restrict__ alpha)
{
    int k = blockIdx.x;
    int s = blk[k], e = blk[k + 1];
    int t = threadIdx.x, wid = t >> 5, lid = t & 31;
    __shared__ float red[4];

    h_file[(size_t)k * DIM + t] = 0.f;   // atomics accumulate later
    if (e - s <= 0) return;

    // pass 1: max
    float m = -3.402823466e38f;
    for (int i = s + t; i < e; i += 128) m = fmaxf(m, g_scores[i]);
    #pragma unroll
    for (int o = 16; o; o >>= 1) m = fmaxf(m, __shfl_xor_sync(0xffffffffu, m, o));
    if (lid == 0) red[wid] = m;
    __syncthreads();
    m = fmaxf(fmaxf(red[0], red[1]), fmaxf(red[2], red[3]));
    __syncthreads();

    // pass 2: sum of exp; stash raw exp into alpha
    float sum = 0.f;
    for (int i = s + t; i < e; i += 128) {
        float ev = __expf(g_scores[i] - m);
        alpha[i] = ev;
        sum += ev;
    }
    #pragma unroll
    for (int o = 16; o; o >>= 1) sum += __shfl_xor_sync(0xffffffffu, sum, o);
    if (lid == 0) red[wid] = sum;
    __syncthreads();
    sum = red[0] + red[1] + red[2] + red[3];
    float inv = 1.0f / sum;

    // pass 3: normalize in place (no cross-warp read hazard: each thread
    // rescales exactly the entries it wrote in pass 2)
    for (int j = s + t; j < e; j += 128) alpha[j] *= inv;
}

// ======= Kernel 2b: uniform-chunk weighted accumulation =======
// CTA covers rows [r0, r0+CHUNK); thread t owns dim t; atomicAdd per segment flush.
__global__ void __launch_bounds__(128)
accum_kernel(const float* __restrict__ h, const int* __restrict__ blk,
             const float* __restrict__ alpha, float* __restrict__ h_file,
             int n, int B)
{
    int r0 = blockIdx.x * CHUNK;
    int r1 = min(n, r0 + CHUNK);
    if (r0 >= r1) return;
    int t = threadIdx.x;

    // largest k with blk[k] <= r0  (blk has B+1 entries, blk[B] = n > r0)
    int lo = 0, hi = B - 1;
    while (lo < hi) {
        int mid = (lo + hi + 1) >> 1;
        if (blk[mid] <= r0) lo = mid; else hi = mid - 1;
    }
    int k = lo;
    int nend = blk[k + 1];

    float acc = 0.f;
    int i = r0;
    while (true) {
        int stop = min(r1, nend);
        // unroll-8 streaming inner loop (same segment)
        for (; i + 8 <= stop; i += 8) {
            float a0 = alpha[i],     a1 = alpha[i + 1];
            float a2 = alpha[i + 2], a3 = alpha[i + 3];
            float a4 = alpha[i + 4], a5 = alpha[i + 5];
            float a6 = alpha[i + 6], a7 = alpha[i + 7];
            float h0 = h[(size_t)(i    ) * DIM + t];
            float h1 = h[(size_t)(i + 1) * DIM + t];
            float h2 = h[(size_t)(i + 2) * DIM + t];
            float h3 = h[(size_t)(i + 3) * DIM + t];
            float h4 = h[(size_t)(i + 4) * DIM + t];
            float h5 = h[(size_t)(i + 5) * DIM + t];
            float h6 = h[(size_t)(i + 6) * DIM + t];
            float h7 = h[(size_t)(i + 7) * DIM + t];
            acc = fmaf(a0, h0, acc); acc = fmaf(a1, h1, acc);
            acc = fmaf(a2, h2, acc); acc = fmaf(a3, h3, acc);
            acc = fmaf(a4, h4, acc); acc = fmaf(a5, h5, acc);
            acc = fmaf(a6, h6, acc); acc = fmaf(a7, h7, acc);
        }
        for (; i < stop; i++)
            acc = fmaf(alpha[i], h[(size_t)i * DIM + t], acc);

        if (stop < r1) {
            // segment boundary strictly inside chunk: flush + advance
            atomicAdd(&h_file[(size_t)k * DIM + t], acc);
            acc = 0.f;
            do { k++; } while (blk[k + 1] <= stop);
            nend = blk[k + 1];
        } else break;
    }
    atomicAdd(&h_file[(size_t)k * DIM + t], acc);
}

// ================= launch =================
extern "C" void kernel_launch(void* const* d_in, const int* in_sizes, int n_in,
                              void* d_out, int out_size)
{
    const float* h   = (const float*)d_in[0];
    const float* W   = (const float*)d_in[1];
    const float* b   = (const float*)d_in[2];
    const float* ctx = (const float*)d_in[3];
    const int*   blk = (const int*)d_in[4];

    int n = in_sizes[0] / DIM;
    if (n > MAX_N) n = MAX_N;
    int B = in_sizes[4] - 1;

    float* out    = (float*)d_out;
    float* h_file = out;
    float* alpha  = out + (size_t)B * DIM;

    cudaFuncSetAttribute(score_kernel,
                         cudaFuncAttributeMaxDynamicSharedMemorySize, SMEM_TOTAL);

    int dev = 0, nsm = 148;
    cudaGetDevice(&dev);
    cudaDeviceGetAttribute(&nsm, cudaDevAttrMultiProcessorCount, dev);

    int ntiles = (n + TILE_M - 1) / TILE_M;
    int grid1 = (nsm < ntiles) ? nsm : ntiles;

    score_kernel<<<grid1, 256, SMEM_TOTAL>>>(h, W, b, ctx, n);
    seg_stats_kernel<<<B, 128>>>(blk, h_file, alpha);
    int gridB = (n + CHUNK - 1) / CHUNK;
    accum_kernel<<<gridB, 128>>>(h, blk, alpha, h_file, n, B);
}

// round 9
// speedup vs baseline: 1.2434x; 1.1548x over previous
#include <cuda_runtime.h>
#include <cuda_bf16.h>
#include <cstdint>

#define DIM 128
#define TILE_M 128
#define MAX_N 1000000
#define CHUNK 512

__device__ float g_scores[MAX_N];

// ---------------- smem layout (kernel 1) ----------------
// W_hi 32K | W_lo 32K | stage0 (A_hi 32K | A_lo 32K) | stage1 (...) | bk | c2 | mbar
#define OFF_W_HI  0
#define OFF_W_LO  32768
#define OFF_STAGE0 65536
#define STAGE_STRIDE 65536
#define OFF_BK    196608          // b[c] * 2*log2(e)
#define OFF_C2    197120          // -2 * ctx[c]
#define OFF_MBAR  197632          // full0, full1, empty0, empty1 (8B each)
#define SMEM_TOTAL (197632 + 256)

#define N_CONS 256                // 8 consumer warps
#define N_PROD 128                // 4 producer warps
#define N_THREADS (N_CONS + N_PROD)

#define K2LOG2E 2.8853900817779268f

// ---------------- helpers ----------------
__device__ __forceinline__ uint32_t smem_to_u32(const void* p) {
    uint32_t a;
    asm("{ .reg .u64 t; cvta.to.shared.u64 t, %1; cvt.u32.u64 %0, t; }"
        : "=r"(a) : "l"(p));
    return a;
}

__device__ __forceinline__ float ex2f(float x) {
    float y; asm("ex2.approx.f32 %0, %1;" : "=f"(y) : "f"(x)); return y;
}
__device__ __forceinline__ float rcpf(float x) {
    float y; asm("rcp.approx.f32 %0, %1;" : "=f"(y) : "f"(x)); return y;
}

// swizzled bf16 tile address: row-major, 256B/row (128 bf16), 16B chunks XOR'd by row&7
__device__ __forceinline__ uint32_t sw_addr(uint32_t base, int row, int kchunk) {
    return base + (uint32_t)row * 256u + (uint32_t)((kchunk ^ (row & 7)) << 4);
}

__device__ __forceinline__ void ldsm4(uint32_t* r, uint32_t addr) {
    asm volatile("ldmatrix.sync.aligned.m8n8.x4.shared.b16 {%0,%1,%2,%3}, [%4];"
        : "=r"(r[0]), "=r"(r[1]), "=r"(r[2]), "=r"(r[3]) : "r"(addr));
}

__device__ __forceinline__ void mma_bf16(float* d, const uint32_t* a, const uint32_t* b) {
    asm volatile(
        "mma.sync.aligned.m16n8k16.row.col.f32.bf16.bf16.f32 "
        "{%0,%1,%2,%3}, {%4,%5,%6,%7}, {%8,%9}, {%0,%1,%2,%3};"
        : "+f"(d[0]), "+f"(d[1]), "+f"(d[2]), "+f"(d[3])
        : "r"(a[0]), "r"(a[1]), "r"(a[2]), "r"(a[3]), "r"(b[0]), "r"(b[1]));
}

#define MBARRIER_INIT(mbar, count) \
    asm volatile("mbarrier.init.shared.b64 [%0], %1;" \
        :: "r"((uint32_t)(mbar)), "r"((uint32_t)(count)) : "memory")

#define MBARRIER_ARRIVE(mbar) \
    asm volatile("mbarrier.arrive.release.cta.shared.b64 _, [%0];" \
        :: "r"((uint32_t)(mbar)) : "memory")

#define MBARRIER_WAIT_PARITY(mbar, parity) do { \
    uint32_t _m = (uint32_t)(mbar), _p = (uint32_t)(parity), _d; \
    asm volatile( \
        "{\n\t.reg .pred p;\n\t" \
        "mbarrier.try_wait.parity.acquire.cta.shared::cta.b64 p, [%1], %2;\n\t" \
        "selp.b32 %0, 1, 0, p;\n\t}" \
        : "=r"(_d) : "r"(_m), "r"(_p) : "memory"); \
    if (!_d) { \
        asm volatile( \
            "{\n\t.reg .pred P1;\n\t" \
            "WL_%=:\n\t" \
            "mbarrier.try_wait.parity.acquire.cta.shared::cta.b64 P1, [%0], %1, 0x989680;\n\t" \
            "@P1 bra.uni WD_%=;\n\t" \
            "bra.uni WL_%=;\n\t" \
            "WD_%=:\n\t}" \
            :: "r"(_m), "r"(_p) : "memory"); \
    } \
} while(0)

union BfU { __nv_bfloat162 b; uint32_t u; };

// Truncation split: hi = top-16-bits bf16 (exact), lo = x - hi (exact fp32) -> bf16 RN.
__device__ __forceinline__ void split_store(char* smem, uint32_t hi_off, uint32_t lo_off,
                                            int r, int q, float4 v) {
    uint32_t xu0 = __float_as_uint(v.x), xu1 = __float_as_uint(v.y);
    uint32_t xu2 = __float_as_uint(v.z), xu3 = __float_as_uint(v.w);
    uint32_t hi01 = (xu0 >> 16) | (xu1 & 0xFFFF0000u);
    uint32_t hi23 = (xu2 >> 16) | (xu3 & 0xFFFF0000u);
    float l0f = v.x - __uint_as_float(xu0 & 0xFFFF0000u);
    float l1f = v.y - __uint_as_float(xu1 & 0xFFFF0000u);
    float l2f = v.z - __uint_as_float(xu2 & 0xFFFF0000u);
    float l3f = v.w - __uint_as_float(xu3 & 0xFFFF0000u);
    BfU lo01, lo23;
    lo01.b = __floats2bfloat162_rn(l0f, l1f);
    lo23.b = __floats2bfloat162_rn(l2f, l3f);
    uint32_t boff = (uint32_t)r * 256u + (uint32_t)(((q >> 1) ^ (r & 7)) << 4)
                  + (uint32_t)((q & 1) << 3);
    *(uint2*)(smem + hi_off + boff) = make_uint2(hi01, hi23);
    *(uint2*)(smem + lo_off + boff) = make_uint2(lo01.u, lo23.u);
}

// ================= Kernel 1 (warp-specialized) =================
// Warps 0-7: consumers. Warp w owns rows [w*16, w*16+16), all 128 cols.
// Warps 8-11: producers. LDG.cs fp32 -> split -> STS into 2-stage A ring.
__global__ void __launch_bounds__(N_THREADS, 1)
score_kernel(const float* __restrict__ h, const float* __restrict__ W,
             const float* __restrict__ b, const float* __restrict__ ctx, int n)
{
    extern __shared__ char smem[];
    uint32_t sb = smem_to_u32(smem);
    int tid = threadIdx.x;
    int wid = tid >> 5, lane = tid & 31;

    // ---- prologue: W split (swizzled), transformed b/ctx, mbarriers ----
    for (int idx = tid; idx < TILE_M * 32; idx += N_THREADS) {
        int r = idx >> 5, q = idx & 31;
        float4 v = *(const float4*)(W + (size_t)r * DIM + q * 4);
        split_store(smem, OFF_W_HI, OFF_W_LO, r, q, v);
    }
    if (tid < DIM) {
        ((float*)(smem + OFF_BK))[tid] = b[tid] * K2LOG2E;
        ((float*)(smem + OFF_C2))[tid] = -2.0f * ctx[tid];
    }
    if (tid == 0) {
        MBARRIER_INIT(sb + OFF_MBAR + 0,  N_PROD);   // full0
        MBARRIER_INIT(sb + OFF_MBAR + 8,  N_PROD);   // full1
        MBARRIER_INIT(sb + OFF_MBAR + 16, N_CONS);   // empty0
        MBARRIER_INIT(sb + OFF_MBAR + 24, N_CONS);   // empty1
    }
    __syncthreads();

    int ntiles = (n + TILE_M - 1) / TILE_M;

    if (wid >= 8) {
        // ================== PRODUCER ==================
        int ptid = tid - N_CONS;          // 0..127
        int st = 0, ph = 1;               // fresh-barrier parity-1 wait passes
        for (int t = blockIdx.x; t < ntiles; t += gridDim.x) {
            int m0 = t * TILE_M;
            int valid = min(TILE_M, n - m0);
            MBARRIER_WAIT_PARITY(sb + OFF_MBAR + 16 + st * 8, ph);
            uint32_t a_hi = OFF_STAGE0 + st * STAGE_STRIDE;
            uint32_t a_lo = a_hi + 32768;
            const float4* src = (const float4*)(h + (size_t)m0 * DIM);
            #pragma unroll
            for (int it = 0; it < 32; it++) {
                int chunk = ptid + it * N_PROD;   // 4096 chunks of 16B
                int r = chunk >> 5, q = chunk & 31;
                float4 v = (r < valid) ? __ldcs(src + chunk)
                                       : make_float4(0.f, 0.f, 0.f, 0.f);
                split_store(smem, a_hi, a_lo, r, q, v);
            }
            MBARRIER_ARRIVE(sb + OFF_MBAR + st * 8);   // full[st]
            st ^= 1; if (st == 0) ph ^= 1;
        }
    } else {
        // ================== CONSUMER ==================
        const float* bkp = (const float*)(smem + OFF_BK);
        const float* c2p = (const float*)(smem + OFF_C2);

        // csum: sum of ctx over this thread's 32 columns (j=0..15, 2 cols each)
        float csum = 0.f;
        {
            int cb = (lane & 3) * 2;
            #pragma unroll
            for (int j = 0; j < 16; j++)
                csum += ctx[j * 8 + cb] + ctx[j * 8 + cb + 1];
        }

        int st = 0, ph = 0;
        for (int t = blockIdx.x; t < ntiles; t += gridDim.x) {
            int m0 = t * TILE_M;
            MBARRIER_WAIT_PARITY(sb + OFF_MBAR + st * 8, ph);   // full[st]
            uint32_t a_hi_b = OFF_STAGE0 + st * STAGE_STRIDE;
            uint32_t a_lo_b = a_hi_b + 32768;

            float acc[16][4];
            #pragma unroll
            for (int j = 0; j < 16; j++)
                #pragma unroll
                for (int e = 0; e < 4; e++) acc[j][e] = 0.f;

            int arow = wid * 16 + (lane & 15);
            int brow = (lane & 7) + ((lane >> 4) << 3);
            int bk_sel = (lane >> 3) & 1;

            #pragma unroll
            for (int ks = 0; ks < 8; ks++) {
                uint32_t a_hi[4], a_lo[4];
                int akch = ks * 2 + (lane >> 4);
                ldsm4(a_hi, sw_addr(sb + a_hi_b, arow, akch));
                ldsm4(a_lo, sw_addr(sb + a_lo_b, arow, akch));
                int bkch = ks * 2 + bk_sel;
                #pragma unroll
                for (int p = 0; p < 8; p++) {
                    uint32_t bh[4], bl[4];
                    ldsm4(bh, sw_addr(sb + OFF_W_HI, p * 16 + brow, bkch));
                    ldsm4(bl, sw_addr(sb + OFF_W_LO, p * 16 + brow, bkch));
                    mma_bf16(acc[2 * p],     a_hi, bh);
                    mma_bf16(acc[2 * p],     a_lo, bh);
                    mma_bf16(acc[2 * p],     a_hi, bl);
                    mma_bf16(acc[2 * p + 1], a_hi, bh + 2);
                    mma_bf16(acc[2 * p + 1], a_lo, bh + 2);
                    mma_bf16(acc[2 * p + 1], a_hi, bl + 2);
                }
            }

            // release stage as soon as smem reads are done (epilogue is reg-only)
            MBARRIER_ARRIVE(sb + OFF_MBAR + 16 + st * 8);   // empty[st]
            st ^= 1; if (st == 0) ph ^= 1;

            // epilogue: tanh(x) = 1 - 2/(1+e^{2x}); 3 FFMA + EX2 + RCP per elem
            float s0 = csum, s1 = csum;
            #pragma unroll
            for (int j = 0; j < 16; j++) {
                int c0 = j * 8 + (lane & 3) * 2;
                float bk0 = bkp[c0], bk1 = bkp[c0 + 1];
                float c20 = c2p[c0], c21 = c2p[c0 + 1];
                s0 += rcpf(1.0f + ex2f(fmaf(acc[j][0], K2LOG2E, bk0))) * c20
                    + rcpf(1.0f + ex2f(fmaf(acc[j][1], K2LOG2E, bk1))) * c21;
                s1 += rcpf(1.0f + ex2f(fmaf(acc[j][2], K2LOG2E, bk0))) * c20
                    + rcpf(1.0f + ex2f(fmaf(acc[j][3], K2LOG2E, bk1))) * c21;
            }
            s0 += __shfl_xor_sync(0xffffffffu, s0, 1);
            s0 += __shfl_xor_sync(0xffffffffu, s0, 2);
            s1 += __shfl_xor_sync(0xffffffffu, s1, 1);
            s1 += __shfl_xor_sync(0xffffffffu, s1, 2);
            if ((lane & 3) == 0) {
                int m = m0 + wid * 16 + (lane >> 2);
                if (m < n)     g_scores[m]     = s0;
                if (m + 8 < n) g_scores[m + 8] = s1;
            }
        }
    }
}

// ======= Kernel 2a: per-segment softmax stats -> normalized alpha; zero h_file =======
__global__ void __launch_bounds__(128)
seg_stats_kernel(const int* __restrict__ blk, float* __restrict__ h_file,
                 float* __restrict__ alpha)
{
    int k = blockIdx.x;
    int s = blk[k], e = blk[k + 1];
    int t = threadIdx.x, wid = t >> 5, lid = t & 31;
    __shared__ float red[4];

    h_file[(size_t)k * DIM + t] = 0.f;   // atomics accumulate later
    if (e - s <= 0) return;

    float m = -3.402823466e38f;
    for (int i = s + t; i < e; i += 128) m = fmaxf(m, g_scores[i]);
    #pragma unroll
    for (int o = 16; o; o >>= 1) m = fmaxf(m, __shfl_xor_sync(0xffffffffu, m, o));
    if (lid == 0) red[wid] = m;
    __syncthreads();
    m = fmaxf(fmaxf(red[0], red[1]), fmaxf(red[2], red[3]));
    __syncthreads();

    float sum = 0.f;
    for (int i = s + t; i < e; i += 128) {
        float ev = __expf(g_scores[i] - m);
        alpha[i] = ev;
        sum += ev;
    }
    #pragma unroll
    for (int o = 16; o; o >>= 1) sum += __shfl_xor_sync(0xffffffffu, sum, o);
    if (lid == 0) red[wid] = sum;
    __syncthreads();
    sum = red[0] + red[1] + red[2] + red[3];
    float inv = 1.0f / sum;

    // normalize in place (each thread rescales exactly what it wrote)
    for (int j = s + t; j < e; j += 128) alpha[j] *= inv;
}

// ======= Kernel 2b: uniform-chunk weighted accumulation (float4, 4 rows/iter) ===
// warp wq handles row i+wq; thread covers cols q*4..q*4+3. atomicAdd at flushes.
__global__ void __launch_bounds__(128)
accum_kernel(const float* __restrict__ h, const int* __restrict__ blk,
             const float* __restrict__ alpha, float* __restrict__ h_file,
             int n, int B)
{
    int r0 = blockIdx.x * CHUNK;
    int r1 = min(n, r0 + CHUNK);
    if (r0 >= r1) return;
    int t = threadIdx.x;
    int wq = t >> 5;          // 0..3: row offset within 4-row group
    int q  = t & 31;          // float4 column index

    // largest k with blk[k] <= r0
    int lo = 0, hi = B - 1;
    while (lo < hi) {
        int mid = (lo + hi + 1) >> 1;
        if (blk[mid] <= r0) lo = mid; else hi = mid - 1;
    }
    int k = lo;
    int nend = blk[k + 1];

    float4 acc = make_float4(0.f, 0.f, 0.f, 0.f);
    int i = r0;
    while (true) {
        int stop = min(r1, nend);
        #pragma unroll 4
        for (; i + 4 <= stop; i += 4) {
            int r = i + wq;
            float a = __ldcs(alpha + r);                 // warp-uniform broadcast
            float4 hv = __ldcs((const float4*)(h + (size_t)r * DIM) + q);
            acc.x = fmaf(a, hv.x, acc.x);
            acc.y = fmaf(a, hv.y, acc.y);
            acc.z = fmaf(a, hv.z, acc.z);
            acc.w = fmaf(a, hv.w, acc.w);
        }
        if (i < stop) {                                   // 1-3 remainder rows
            int r = i + wq;
            if (r < stop) {
                float a = __ldcs(alpha + r);
                float4 hv = __ldcs((const float4*)(h + (size_t)r * DIM) + q);
                acc.x = fmaf(a, hv.x, acc.x);
                acc.y = fmaf(a, hv.y, acc.y);
                acc.z = fmaf(a, hv.z, acc.z);
                acc.w = fmaf(a, hv.w, acc.w);
            }
            i = stop;
        }
        if (stop < r1) {
            float* dst = h_file + (size_t)k * DIM + q * 4;
            atomicAdd(dst + 0, acc.x);
            atomicAdd(dst + 1, acc.y);
            atomicAdd(dst + 2, acc.z);
            atomicAdd(dst + 3, acc.w);
            acc = make_float4(0.f, 0.f, 0.f, 0.f);
            do { k++; } while (blk[k + 1] <= stop);
            nend = blk[k + 1];
        } else break;
    }
    float* dst = h_file + (size_t)k * DIM + q * 4;
    atomicAdd(dst + 0, acc.x);
    atomicAdd(dst + 1, acc.y);
    atomicAdd(dst + 2, acc.z);
    atomicAdd(dst + 3, acc.w);
}

// ================= launch =================
extern "C" void kernel_launch(void* const* d_in, const int* in_sizes, int n_in,
                              void* d_out, int out_size)
{
    const float* h   = (const float*)d_in[0];
    const float* W   = (const float*)d_in[1];
    const float* b   = (const float*)d_in[2];
    const float* ctx = (const float*)d_in[3];
    const int*   blk = (const int*)d_in[4];

    int n = in_sizes[0] / DIM;
    if (n > MAX_N) n = MAX_N;
    int B = in_sizes[4] - 1;

    float* out    = (float*)d_out;
    float* h_file = out;
    float* alpha  = out + (size_t)B * DIM;

    cudaFuncSetAttribute(score_kernel,
                         cudaFuncAttributeMaxDynamicSharedMemorySize, SMEM_TOTAL);

    int dev = 0, nsm = 148;
    cudaGetDevice(&dev);
    cudaDeviceGetAttribute(&nsm, cudaDevAttrMultiProcessorCount, dev);

    int ntiles = (n + TILE_M - 1) / TILE_M;
    int grid1 = (nsm < ntiles) ? nsm : ntiles;

    score_kernel<<<grid1, N_THREADS, SMEM_TOTAL>>>(h, W, b, ctx, n);
    seg_stats_kernel<<<B, 128>>>(blk, h_file, alpha);
    int gridB = (n + CHUNK - 1) / CHUNK;
    accum_kernel<<<gridB, 128>>>(h, blk, alpha, h_file, n, B);
}